// round 15
// baseline (speedup 1.0000x reference)
#include <cuda_runtime.h>
#include <cuda_fp16.h>
#include <cstdint>

// Batch Conv1D hybrid: HMMA (mma.sync fp16/fp32) + FFMA (fp32 SGEMM) pipes
// used CONCURRENTLY in one kernel. Legacy HMMA caps at 512 MAC/cyc/SM (R12 at
// 93% of it); the fp32 FMA pipe (~87 MAC/cyc/SM sustained, R1) is idle there.
// Rows 0-895 -> R12 tap-reuse HMMA path; rows 896-1021 -> R1 FFMA SGEMM path.
// Per image 14 HMMA + 2 FFMA CTAs interleaved in bid order.

namespace {

constexpr int LOUT = 1022;
constexpr int NTHREADS = 256;

// ---- HMMA-path smem layout (R12) ----
constexpr int A_STRIDE = 80;
constexpr int A_BYTES  = 10496;
constexpr int B_STRIDE = 272;
constexpr int B_BYTES  = 8704;
constexpr int F_STRIDE = 144;
constexpr int F_BYTES  = 18816;
constexpr int OFF_A = 0;
constexpr int OFF_B = 2 * A_BYTES;
constexpr int OFF_F = OFF_B + 3 * B_BYTES;
constexpr int SMEM_TOTAL = OFF_F + 2 * F_BYTES;   // 84736 (covers FFMA's 32KB)

__device__ __half g_wf16[768 * 256];

// ---------------- PTX helpers ----------------

__device__ __forceinline__ uint32_t smem_u32(const void* p) {
    return (uint32_t)__cvta_generic_to_shared(p);
}
__device__ __forceinline__ void cp16(uint32_t dst, const void* src) {
    asm volatile("cp.async.cg.shared.global [%0], [%1], 16;" :: "r"(dst), "l"(src));
}
__device__ __forceinline__ void cp_commit() {
    asm volatile("cp.async.commit_group;" ::: "memory");
}
__device__ __forceinline__ void cp_wait1() {
    asm volatile("cp.async.wait_group 1;" ::: "memory");
}
__device__ __forceinline__ void cp_wait0() {
    asm volatile("cp.async.wait_group 0;" ::: "memory");
}
__device__ __forceinline__ void ldsm4(uint32_t (&r)[4], uint32_t addr) {
    asm volatile("ldmatrix.sync.aligned.m8n8.x4.shared.b16 {%0,%1,%2,%3}, [%4];"
                 : "=r"(r[0]), "=r"(r[1]), "=r"(r[2]), "=r"(r[3]) : "r"(addr));
}
__device__ __forceinline__ void ldsm4t(uint32_t (&r)[4], uint32_t addr) {
    asm volatile("ldmatrix.sync.aligned.m8n8.x4.trans.shared.b16 {%0,%1,%2,%3}, [%4];"
                 : "=r"(r[0]), "=r"(r[1]), "=r"(r[2]), "=r"(r[3]) : "r"(addr));
}
__device__ __forceinline__ void mma16816(float (&c)[4], const uint32_t (&a)[4],
                                         uint32_t b0, uint32_t b1) {
    asm volatile(
        "mma.sync.aligned.m16n8k16.row.col.f32.f16.f16.f32 "
        "{%0,%1,%2,%3}, {%4,%5,%6,%7}, {%8,%9}, {%0,%1,%2,%3};"
        : "+f"(c[0]), "+f"(c[1]), "+f"(c[2]), "+f"(c[3])
        : "r"(a[0]), "r"(a[1]), "r"(a[2]), "r"(a[3]), "r"(b0), "r"(b1));
}
__device__ __forceinline__ uint32_t pack_h2(float a, float b) {
    __half2 h = __floats2half2_rn(a, b);
    return *(uint32_t*)&h;
}

// ---------------- pre-pass: W fp32 -> fp16 (tiny) ----------------

__global__ void wconv_kernel(const float* __restrict__ W) {
    int i = blockIdx.x * 256 + threadIdx.x;
    g_wf16[i] = __float2half_rn(W[i]);
}

// ================= HMMA path (R12 verbatim, rows l0..l0+127) =================

__device__ void hmma_body(uint8_t* smem, const float* xb, const float* bias,
                          float* ob, int f0, int l0)
{
    const uint32_t sm = smem_u32(smem);
    const int tid  = threadIdx.x;
    const int wid  = tid >> 5;
    const int lane = tid & 31;

    const int wm = (wid >> 1) * 32;
    const int wn = (wid & 1) * 64;

    const uint32_t a_lane = (uint32_t)(wm + (lane & 15)) * A_STRIDE + (lane >> 4) * 16;
    const uint32_t b_lane = (uint32_t)(lane & 15) * B_STRIDE
                          + (uint32_t)(wn + (lane >> 4) * 8) * 2;

    const int b_row = tid >> 3;
    const int b_cg  = tid & 7;
    const uint32_t b_dst = (uint32_t)b_row * B_STRIDE + b_cg * 32;

    auto stageB = [&](int s) {
        const int c = s / 3, tap = s - 3 * c;
        const int kr = tap * 256 + c * 32 + b_row;
        const __half* src = g_wf16 + (size_t)kr * 256 + f0 + b_cg * 16;
        const uint32_t d = sm + OFF_B + (s % 3) * B_BYTES + b_dst;
        cp16(d,      src);
        cp16(d + 16, src + 8);
    };

    auto stageAF32 = [&](int c) {
        const int buf = c & 1;
        #pragma unroll
        for (int rep = 0; rep < 2; ++rep) {
            const int item = tid + rep * 256;
            if (rep == 0 || tid < 4) {
                const int row = item >> 1, seg = item & 1;
                int xr = l0 + row;
                if (xr > 1023) xr = 1023;
                const float* src = xb + (size_t)xr * 256 + c * 32 + seg * 16;
                const uint32_t d = sm + OFF_F + buf * F_BYTES
                                 + (uint32_t)row * F_STRIDE + seg * 64;
                cp16(d,      src);
                cp16(d + 16, src + 4);
                cp16(d + 32, src + 8);
                cp16(d + 48, src + 12);
            }
        }
    };

    auto convA = [&](int c) {
        const int buf = c & 1;
        const uint8_t* fb = smem + OFF_F + buf * F_BYTES;
        uint8_t*       ab = smem + OFF_A + buf * A_BYTES;
        #pragma unroll
        for (int rep = 0; rep < 2; ++rep) {
            const int item = tid + rep * 256;
            if (rep == 0 || tid < 4) {
                const int row = item >> 1, seg = item & 1;
                const float* s = (const float*)(fb + (uint32_t)row * F_STRIDE + seg * 64);
                float4 v0 = *(const float4*)(s);
                float4 v1 = *(const float4*)(s + 4);
                float4 v2 = *(const float4*)(s + 8);
                float4 v3 = *(const float4*)(s + 12);
                uint4 u0, u1;
                u0.x = pack_h2(v0.x, v0.y); u0.y = pack_h2(v0.z, v0.w);
                u0.z = pack_h2(v1.x, v1.y); u0.w = pack_h2(v1.z, v1.w);
                u1.x = pack_h2(v2.x, v2.y); u1.y = pack_h2(v2.z, v2.w);
                u1.z = pack_h2(v3.x, v3.y); u1.w = pack_h2(v3.z, v3.w);
                uint8_t* d = ab + (uint32_t)row * A_STRIDE + seg * 32;
                *(uint4*)(d)      = u0;
                *(uint4*)(d + 16) = u1;
            }
        }
    };

    float acc[2][8][4];
    #pragma unroll
    for (int mt = 0; mt < 2; ++mt)
        #pragma unroll
        for (int nt = 0; nt < 8; ++nt)
            #pragma unroll
            for (int q = 0; q < 4; ++q)
                acc[mt][nt][q] = 0.f;

    stageB(0);
    cp_commit();
    stageB(1);
    stageAF32(0);
    cp_commit();
    cp_wait0();
    __syncthreads();
    convA(0);
    __syncthreads();

    for (int c = 0; c < 8; ++c) {
        #pragma unroll
        for (int tap = 0; tap < 3; ++tap) {
            const int s = c * 3 + tap;

            if (s + 2 < 24) stageB(s + 2);
            if (tap == 0 && c < 7) stageAF32(c + 1);
            cp_commit();

            const uint32_t sA = sm + OFF_A + (c & 1) * A_BYTES + (uint32_t)tap * A_STRIDE;
            const uint32_t sB = sm + OFF_B + (s % 3) * B_BYTES;
            #pragma unroll
            for (int ks = 0; ks < 2; ++ks) {
                uint32_t af[2][4];
                ldsm4(af[0], sA + a_lane + ks * 32);
                ldsm4(af[1], sA + a_lane + 16 * A_STRIDE + ks * 32);
                uint32_t bf[4][4];
                #pragma unroll
                for (int n2 = 0; n2 < 4; ++n2)
                    ldsm4t(bf[n2], sB + b_lane + ks * (16 * B_STRIDE) + n2 * 32);
                #pragma unroll
                for (int mt = 0; mt < 2; ++mt)
                    #pragma unroll
                    for (int n2 = 0; n2 < 4; ++n2) {
                        mma16816(acc[mt][2 * n2],     af[mt], bf[n2][0], bf[n2][1]);
                        mma16816(acc[mt][2 * n2 + 1], af[mt], bf[n2][2], bf[n2][3]);
                    }
            }

            if (tap == 2 && c < 7) convA(c + 1);

            if (s < 23) cp_wait1();
            __syncthreads();
        }
    }

    const int g  = lane >> 2;
    const int tq = lane & 3;
    #pragma unroll
    for (int nt = 0; nt < 8; ++nt) {
        const int col = f0 + wn + nt * 8 + tq * 2;
        const float b0 = __ldg(bias + col);
        const float b1 = __ldg(bias + col + 1);
        #pragma unroll
        for (int mt = 0; mt < 2; ++mt) {
            const int r = l0 + wm + mt * 16 + g;
            if (r < LOUT) {
                float2 v = make_float2(acc[mt][nt][0] + b0, acc[mt][nt][1] + b1);
                *(float2*)(ob + (size_t)r * 256 + col) = v;
            }
            if (r + 8 < LOUT) {
                float2 v = make_float2(acc[mt][nt][2] + b0, acc[mt][nt][3] + b1);
                *(float2*)(ob + (size_t)(r + 8) * 256 + col) = v;
            }
        }
    }
}

// ================= FFMA path (R1 verbatim, rows 896..1021) =================

__device__ void ffma_body(uint8_t* smem, const float* xb, const float* w32,
                          const float* bias, float* ob, int f0)
{
    // As/Bs: [2][16][128] floats each (16KB each)
    float* As = (float*)smem;
    float* Bs = (float*)(smem + 16384);
    auto A = [&](int b, int k, int m) -> float& { return As[(b * 16 + k) * 128 + m]; };
    auto Bv = [&](int b, int k, int n) -> float& { return Bs[(b * 16 + k) * 128 + n]; };

    const int l0 = 896;
    const int tid = threadIdx.x;
    const int tx  = tid & 15;
    const int ty  = tid >> 4;

    const int  a_row   = tid >> 1;
    const int  a_k     = (tid & 1) * 8;
    const bool a_valid = (l0 + a_row) < LOUT;
    const float* a_src = xb + (size_t)(l0 + a_row) * 256 + a_k;

    const int b_k = tid >> 4;
    const int b_f = (tid & 15) * 4;
    const float* b_src = w32 + (size_t)b_k * 256 + (f0 + b_f);

    float4 ra0, ra1, rb0, rb1;

    {
        if (a_valid) {
            ra0 = *(const float4*)(a_src);
            ra1 = *(const float4*)(a_src + 4);
        } else {
            ra0 = make_float4(0.f, 0.f, 0.f, 0.f);
            ra1 = make_float4(0.f, 0.f, 0.f, 0.f);
        }
        rb0 = *(const float4*)(b_src);
        rb1 = *(const float4*)(b_src + 64);

        A(0, a_k + 0, a_row) = ra0.x; A(0, a_k + 1, a_row) = ra0.y;
        A(0, a_k + 2, a_row) = ra0.z; A(0, a_k + 3, a_row) = ra0.w;
        A(0, a_k + 4, a_row) = ra1.x; A(0, a_k + 5, a_row) = ra1.y;
        A(0, a_k + 6, a_row) = ra1.z; A(0, a_k + 7, a_row) = ra1.w;
        *(float4*)(&Bv(0, b_k, b_f))      = rb0;
        *(float4*)(&Bv(0, b_k, b_f + 64)) = rb1;
    }
    __syncthreads();

    float acc[8][8];
    #pragma unroll
    for (int i = 0; i < 8; ++i)
        #pragma unroll
        for (int j = 0; j < 8; ++j)
            acc[i][j] = 0.f;

    for (int t = 0; t < 48; ++t) {
        const int cur = t & 1;
        const bool more = (t + 1) < 48;

        if (more) {
            const int kk = (t + 1) * 16;
            if (a_valid) {
                ra0 = *(const float4*)(a_src + kk);
                ra1 = *(const float4*)(a_src + kk + 4);
            } else {
                ra0 = make_float4(0.f, 0.f, 0.f, 0.f);
                ra1 = make_float4(0.f, 0.f, 0.f, 0.f);
            }
            rb0 = *(const float4*)(b_src + (size_t)kk * 256);
            rb1 = *(const float4*)(b_src + (size_t)kk * 256 + 64);
        }

        #pragma unroll
        for (int k = 0; k < 16; ++k) {
            float a[8], b[8];
            *(float4*)(a)     = *(const float4*)(&A(cur, k, ty * 8));
            *(float4*)(a + 4) = *(const float4*)(&A(cur, k, ty * 8 + 4));
            *(float4*)(b)     = *(const float4*)(&Bv(cur, k, tx * 8));
            *(float4*)(b + 4) = *(const float4*)(&Bv(cur, k, tx * 8 + 4));
            #pragma unroll
            for (int i = 0; i < 8; ++i)
                #pragma unroll
                for (int j = 0; j < 8; ++j)
                    acc[i][j] += a[i] * b[j];
        }

        if (more) {
            const int nxt = cur ^ 1;
            A(nxt, a_k + 0, a_row) = ra0.x; A(nxt, a_k + 1, a_row) = ra0.y;
            A(nxt, a_k + 2, a_row) = ra0.z; A(nxt, a_k + 3, a_row) = ra0.w;
            A(nxt, a_k + 4, a_row) = ra1.x; A(nxt, a_k + 5, a_row) = ra1.y;
            A(nxt, a_k + 6, a_row) = ra1.z; A(nxt, a_k + 7, a_row) = ra1.w;
            *(float4*)(&Bv(nxt, b_k, b_f))      = rb0;
            *(float4*)(&Bv(nxt, b_k, b_f + 64)) = rb1;
            __syncthreads();
        }
    }

    const float* bp = bias + f0 + tx * 8;
    const float4 bv0 = *(const float4*)(bp);
    const float4 bv1 = *(const float4*)(bp + 4);

    #pragma unroll
    for (int i = 0; i < 8; ++i) {
        const int l = l0 + ty * 8 + i;
        if (l < LOUT) {
            float4 v0, v1;
            v0.x = acc[i][0] + bv0.x; v0.y = acc[i][1] + bv0.y;
            v0.z = acc[i][2] + bv0.z; v0.w = acc[i][3] + bv0.w;
            v1.x = acc[i][4] + bv1.x; v1.y = acc[i][5] + bv1.y;
            v1.z = acc[i][6] + bv1.z; v1.w = acc[i][7] + bv1.w;
            float* op = ob + (size_t)l * 256 + f0 + tx * 8;
            *(float4*)(op)     = v0;
            *(float4*)(op + 4) = v1;
        }
    }
}

// ================= combined kernel =================

__global__ __launch_bounds__(NTHREADS, 2)
void conv1d_hybrid_kernel(const float* __restrict__ x,
                          const float* __restrict__ w32,
                          const float* __restrict__ bias,
                          float* __restrict__ out)
{
    extern __shared__ __align__(128) uint8_t smem[];

    const int bx  = blockIdx.x;           // 0..15
    const int img = blockIdx.y;

    const float* xb = x   + (size_t)img * (1024 * 256);
    float*       ob = out + (size_t)img * (LOUT * 256);

    if (bx < 14) {
        // HMMA: rows 0..895 (7 m-tiles), 2 f-tiles
        const int f0 = (bx & 1) * 128;
        const int l0 = (bx >> 1) * 128;
        hmma_body(smem, xb, bias, ob, f0, l0);
    } else {
        // FFMA: rows 896..1021, 2 f-tiles
        const int f0 = (bx - 14) * 128;
        ffma_body(smem, xb, w32, bias, ob, f0);
    }
}

}  // namespace

extern "C" void kernel_launch(void* const* d_in, const int* in_sizes, int n_in,
                              void* d_out, int out_size)
{
    const float* x  = (const float*)d_in[0];   // [8,32,1024,256]
    const float* w  = (const float*)d_in[1];   // [3,256,256]
    const float* b  = (const float*)d_in[2];   // [256]
    float* out      = (float*)d_out;           // [8,32,1022,256]

    wconv_kernel<<<768, 256>>>(w);             // tiny: W fp32 -> fp16

    cudaFuncSetAttribute(conv1d_hybrid_kernel,
                         cudaFuncAttributeMaxDynamicSharedMemorySize, SMEM_TOTAL);

    dim3 grid(16, 256);                        // 14 HMMA + 2 FFMA CTAs per image
    conv1d_hybrid_kernel<<<grid, NTHREADS, SMEM_TOTAL>>>(x, w, b, out);
}

// round 16
// speedup vs baseline: 1.8160x; 1.8160x over previous
#include <cuda_runtime.h>
#include <cuda_fp16.h>
#include <cstdint>

// Batch Conv1D, implicit-im2col GEMM on mma.sync (HMMA fp16 in / fp32 acc).
// Round 16: R12 made PERSISTENT. 296 CTAs (2/SM), each owns tiles b, b+296, ...
// of the 4096 (f0 invariant per CTA since stride is even -> B staging and its
// mod-3 slot parity continue across tile boundaries unchanged; 24%3==0).
// Cross-tile pipeline: next tile's B(0),B(1) staged as steps 24,25; A chunk 0
// staged/converted at the c==7 boundary. Saves 13.8x prologues + wave
// transitions; inner MMA step is byte-identical to R12 (364.7us, at ~102% of
// the 512 MAC/cyc/SM legacy-HMMA dispatch floor).

namespace {

constexpr int LOUT = 1022;
constexpr int NTHREADS = 256;
constexpr int NCTA   = 296;              // 2 per SM on 148; fully resident on 152
constexpr int NTILE  = 4096;             // 2 f-tiles x 8 m-tiles x 256 images

constexpr int A_STRIDE = 80;
constexpr int A_BYTES  = 10496;
constexpr int B_STRIDE = 272;
constexpr int B_BYTES  = 8704;
constexpr int F_STRIDE = 144;
constexpr int F_BYTES  = 18816;

constexpr int OFF_A = 0;
constexpr int OFF_B = 2 * A_BYTES;
constexpr int OFF_F = OFF_B + 3 * B_BYTES;
constexpr int SMEM_TOTAL = OFF_F + 2 * F_BYTES;   // 84736 -> 2 CTAs/SM

__device__ __half g_wf16[768 * 256];

// ---------------- PTX helpers ----------------

__device__ __forceinline__ uint32_t smem_u32(const void* p) {
    return (uint32_t)__cvta_generic_to_shared(p);
}
__device__ __forceinline__ void cp16(uint32_t dst, const void* src) {
    asm volatile("cp.async.cg.shared.global [%0], [%1], 16;" :: "r"(dst), "l"(src));
}
__device__ __forceinline__ void cp_commit() {
    asm volatile("cp.async.commit_group;" ::: "memory");
}
__device__ __forceinline__ void cp_wait1() {
    asm volatile("cp.async.wait_group 1;" ::: "memory");
}
__device__ __forceinline__ void cp_wait0() {
    asm volatile("cp.async.wait_group 0;" ::: "memory");
}
__device__ __forceinline__ void ldsm4(uint32_t (&r)[4], uint32_t addr) {
    asm volatile("ldmatrix.sync.aligned.m8n8.x4.shared.b16 {%0,%1,%2,%3}, [%4];"
                 : "=r"(r[0]), "=r"(r[1]), "=r"(r[2]), "=r"(r[3]) : "r"(addr));
}
__device__ __forceinline__ void ldsm4t(uint32_t (&r)[4], uint32_t addr) {
    asm volatile("ldmatrix.sync.aligned.m8n8.x4.trans.shared.b16 {%0,%1,%2,%3}, [%4];"
                 : "=r"(r[0]), "=r"(r[1]), "=r"(r[2]), "=r"(r[3]) : "r"(addr));
}
__device__ __forceinline__ void mma16816(float (&c)[4], const uint32_t (&a)[4],
                                         uint32_t b0, uint32_t b1) {
    asm volatile(
        "mma.sync.aligned.m16n8k16.row.col.f32.f16.f16.f32 "
        "{%0,%1,%2,%3}, {%4,%5,%6,%7}, {%8,%9}, {%0,%1,%2,%3};"
        : "+f"(c[0]), "+f"(c[1]), "+f"(c[2]), "+f"(c[3])
        : "r"(a[0]), "r"(a[1]), "r"(a[2]), "r"(a[3]), "r"(b0), "r"(b1));
}
__device__ __forceinline__ uint32_t pack_h2(float a, float b) {
    __half2 h = __floats2half2_rn(a, b);
    return *(uint32_t*)&h;
}

// ---------------- pre-pass: W fp32 -> fp16 (tiny) ----------------

__global__ void wconv_kernel(const float* __restrict__ W) {
    int i = blockIdx.x * 256 + threadIdx.x;
    g_wf16[i] = __float2half_rn(W[i]);
}

// ---------------- persistent GEMM ----------------

__global__ __launch_bounds__(NTHREADS, 2)
void conv1d_persist_kernel(const float* __restrict__ x,
                           const float* __restrict__ bias,
                           float* __restrict__ out)
{
    extern __shared__ __align__(128) uint8_t smem[];
    const uint32_t sm = smem_u32(smem);

    const int tid  = threadIdx.x;
    const int wid  = tid >> 5;
    const int lane = tid & 31;

    // f0 is invariant for this CTA (tile stride 296 is even)
    const int f0 = (blockIdx.x & 1) * 128;

    const int wm = (wid >> 1) * 32;
    const int wn = (wid & 1) * 64;

    const uint32_t a_lane = (uint32_t)(wm + (lane & 15)) * A_STRIDE + (lane >> 4) * 16;
    const uint32_t b_lane = (uint32_t)(lane & 15) * B_STRIDE
                          + (uint32_t)(wn + (lane >> 4) * 8) * 2;

    const int b_row = tid >> 3;
    const int b_cg  = tid & 7;
    const uint32_t b_dst = (uint32_t)b_row * B_STRIDE + b_cg * 32;

    auto stageB = [&](int s) {                       // tile-independent
        const int c = s / 3, tap = s - 3 * c;
        const int kr = tap * 256 + c * 32 + b_row;
        const __half* src = g_wf16 + (size_t)kr * 256 + f0 + b_cg * 16;
        const uint32_t d = sm + OFF_B + (s % 3) * B_BYTES + b_dst;
        cp16(d,      src);
        cp16(d + 16, src + 8);
    };

    auto stageAF32 = [&](int c, const float* xb2, int l02) {
        const int buf = c & 1;
        #pragma unroll
        for (int rep = 0; rep < 2; ++rep) {
            const int item = tid + rep * 256;        // 260 half-rows
            if (rep == 0 || tid < 4) {
                const int row = item >> 1, seg = item & 1;
                int xr = l02 + row;
                if (xr > 1023) xr = 1023;            // feeds only guarded outputs
                const float* src = xb2 + (size_t)xr * 256 + c * 32 + seg * 16;
                const uint32_t d = sm + OFF_F + buf * F_BYTES
                                 + (uint32_t)row * F_STRIDE + seg * 64;
                cp16(d,      src);
                cp16(d + 16, src + 4);
                cp16(d + 32, src + 8);
                cp16(d + 48, src + 12);
            }
        }
    };

    auto convA = [&](int c) {
        const int buf = c & 1;
        const uint8_t* fb = smem + OFF_F + buf * F_BYTES;
        uint8_t*       ab = smem + OFF_A + buf * A_BYTES;
        #pragma unroll
        for (int rep = 0; rep < 2; ++rep) {
            const int item = tid + rep * 256;
            if (rep == 0 || tid < 4) {
                const int row = item >> 1, seg = item & 1;
                const float* s = (const float*)(fb + (uint32_t)row * F_STRIDE + seg * 64);
                float4 v0 = *(const float4*)(s);
                float4 v1 = *(const float4*)(s + 4);
                float4 v2 = *(const float4*)(s + 8);
                float4 v3 = *(const float4*)(s + 12);
                uint4 u0, u1;
                u0.x = pack_h2(v0.x, v0.y); u0.y = pack_h2(v0.z, v0.w);
                u0.z = pack_h2(v1.x, v1.y); u0.w = pack_h2(v1.z, v1.w);
                u1.x = pack_h2(v2.x, v2.y); u1.y = pack_h2(v2.z, v2.w);
                u1.z = pack_h2(v3.x, v3.y); u1.w = pack_h2(v3.z, v3.w);
                uint8_t* d = ab + (uint32_t)row * A_STRIDE + seg * 32;
                *(uint4*)(d)      = u0;
                *(uint4*)(d + 16) = u1;
            }
        }
    };

    float acc[2][8][4];
    #pragma unroll
    for (int mt = 0; mt < 2; ++mt)
        #pragma unroll
        for (int nt = 0; nt < 8; ++nt)
            #pragma unroll
            for (int q = 0; q < 4; ++q)
                acc[mt][nt][q] = 0.f;

    // ---- first tile + prologue ----
    int tile = blockIdx.x;
    const float* xb = x + (size_t)(tile >> 4) * (1024 * 256);
    int l0 = ((tile >> 1) & 7) * 128;

    stageB(0);
    cp_commit();
    stageB(1);
    stageAF32(0, xb, l0);
    cp_commit();
    cp_wait0();
    __syncthreads();
    convA(0);
    __syncthreads();

    for (;;) {
        const int ntile = tile + NCTA;
        const bool has_next = ntile < NTILE;
        const float* xbn = x;                 // dummy init
        int l0n = 0;
        if (has_next) {
            xbn = x + (size_t)(ntile >> 4) * (1024 * 256);
            l0n = ((ntile >> 1) & 7) * 128;
        }
        float* ob = out + (size_t)(tile >> 4) * (LOUT * 256);

        for (int c = 0; c < 8; ++c) {
            #pragma unroll
            for (int tap = 0; tap < 3; ++tap) {
                const int s = c * 3 + tap;
                const int s2 = s + 2;

                // B staged 2 steps ahead; next tile's pattern == steps 0,1
                if (s2 < 24)           stageB(s2);
                else if (has_next)     stageB(s2 - 24);
                // A fp32 staged 1 chunk (3 steps) ahead
                if (tap == 0) {
                    if (c < 7)             stageAF32(c + 1, xb, l0);
                    else if (has_next)     stageAF32(0, xbn, l0n);
                }
                cp_commit();

                // ---- MMA block (R12 verbatim) ----
                const uint32_t sA = sm + OFF_A + (c & 1) * A_BYTES
                                  + (uint32_t)tap * A_STRIDE;
                const uint32_t sB = sm + OFF_B + (s % 3) * B_BYTES;
                #pragma unroll
                for (int ks = 0; ks < 2; ++ks) {
                    uint32_t af[2][4];
                    ldsm4(af[0], sA + a_lane + ks * 32);
                    ldsm4(af[1], sA + a_lane + 16 * A_STRIDE + ks * 32);
                    uint32_t bf[4][4];
                    #pragma unroll
                    for (int n2 = 0; n2 < 4; ++n2)
                        ldsm4t(bf[n2], sB + b_lane + ks * (16 * B_STRIDE) + n2 * 32);
                    #pragma unroll
                    for (int mt = 0; mt < 2; ++mt)
                        #pragma unroll
                        for (int n2 = 0; n2 < 4; ++n2) {
                            mma16816(acc[mt][2 * n2],     af[mt], bf[n2][0], bf[n2][1]);
                            mma16816(acc[mt][2 * n2 + 1], af[mt], bf[n2][2], bf[n2][3]);
                        }
                }

                // convert next chunk's A on the idle buffer
                if (tap == 2) {
                    if (c < 7)             convA(c + 1);
                    else if (has_next)     convA(0);
                }

                if (s < 23 || has_next) cp_wait1();
                else                    cp_wait0();
                __syncthreads();
            }
        }

        // ---- epilogue for this tile ----
        {
            const int g  = lane >> 2;
            const int tq = lane & 3;
            #pragma unroll
            for (int nt = 0; nt < 8; ++nt) {
                const int col = f0 + wn + nt * 8 + tq * 2;
                const float b0 = __ldg(bias + col);
                const float b1 = __ldg(bias + col + 1);
                #pragma unroll
                for (int mt = 0; mt < 2; ++mt) {
                    const int r = l0 + wm + mt * 16 + g;
                    if (r < LOUT) {
                        float2 v = make_float2(acc[mt][nt][0] + b0, acc[mt][nt][1] + b1);
                        *(float2*)(ob + (size_t)r * 256 + col) = v;
                    }
                    if (r + 8 < LOUT) {
                        float2 v = make_float2(acc[mt][nt][2] + b0, acc[mt][nt][3] + b1);
                        *(float2*)(ob + (size_t)(r + 8) * 256 + col) = v;
                    }
                }
            }
        }

        if (!has_next) break;

        // reset accumulators, advance tile
        #pragma unroll
        for (int mt = 0; mt < 2; ++mt)
            #pragma unroll
            for (int nt = 0; nt < 8; ++nt)
                #pragma unroll
                for (int q = 0; q < 4; ++q)
                    acc[mt][nt][q] = 0.f;
        tile = ntile;
        xb   = xbn;
        l0   = l0n;
        __syncthreads();   // all warps past epilogue before next tile's steps
    }
}

}  // namespace

extern "C" void kernel_launch(void* const* d_in, const int* in_sizes, int n_in,
                              void* d_out, int out_size)
{
    const float* x  = (const float*)d_in[0];   // [8,32,1024,256]
    const float* w  = (const float*)d_in[1];   // [3,256,256]
    const float* b  = (const float*)d_in[2];   // [256]
    float* out      = (float*)d_out;           // [8,32,1022,256]

    wconv_kernel<<<768, 256>>>(w);             // tiny: W fp32 -> fp16

    cudaFuncSetAttribute(conv1d_persist_kernel,
                         cudaFuncAttributeMaxDynamicSharedMemorySize, SMEM_TOTAL);

    conv1d_persist_kernel<<<NCTA, NTHREADS, SMEM_TOTAL>>>(x, b, out);
}

// round 17
// speedup vs baseline: 2.0228x; 1.1139x over previous
#include <cuda_runtime.h>
#include <cuda_fp16.h>
#include <cstdint>

// Batch Conv1D, implicit-im2col GEMM on mma.sync (HMMA fp16 in / fp32 acc).
// Round 17: R12 with CHUNK-granular synchronization (24 -> 8 sync points/tile).
// Insight: stageAF32 and convA use the identical thread->(row,seg) mapping, so
// after cp_wait0 each thread converts its own staged bytes -> no barrier needed
// before convA. B double-buffered at chunk granularity (6 slots = 2 halves x 3
// taps); one cp.async group per chunk {B(c+1) all taps + Af32(c+1)}; all 3 tap
// MMA sub-blocks (96 mma.sync) run without internal barriers; end of chunk:
// wait0 -> convA(c+1) -> single syncthreads.
// Legacy HMMA dispatch floor: 512 MAC/cyc/SM -> 357us GEMM; R12 at 364.4.

namespace {

constexpr int LOUT = 1022;
constexpr int NTHREADS = 256;

constexpr int A_STRIDE = 80;                // 32 fp16 + 16B pad
constexpr int A_BYTES  = 10496;             // 130*80 padded
constexpr int B_STRIDE = 272;               // 128 fp16 + 16B pad
constexpr int B_BYTES  = 8704;              // 32*272
constexpr int F_STRIDE = 144;               // 32 fp32 + 16B pad
constexpr int F_BYTES  = 18816;             // 130*144 padded

constexpr int OFF_A = 0;                    // 2 bufs
constexpr int OFF_B = 2 * A_BYTES;          // 6 slots (2 halves x 3 taps)
constexpr int OFF_F = OFF_B + 6 * B_BYTES;  // 2 bufs
constexpr int SMEM_TOTAL = OFF_F + 2 * F_BYTES;   // 110848 -> 2 CTAs/SM

__device__ __half g_wf16[768 * 256];

// ---------------- PTX helpers ----------------

__device__ __forceinline__ uint32_t smem_u32(const void* p) {
    return (uint32_t)__cvta_generic_to_shared(p);
}
__device__ __forceinline__ void cp16(uint32_t dst, const void* src) {
    asm volatile("cp.async.cg.shared.global [%0], [%1], 16;" :: "r"(dst), "l"(src));
}
__device__ __forceinline__ void cp_commit() {
    asm volatile("cp.async.commit_group;" ::: "memory");
}
__device__ __forceinline__ void cp_wait0() {
    asm volatile("cp.async.wait_group 0;" ::: "memory");
}
__device__ __forceinline__ void ldsm4(uint32_t (&r)[4], uint32_t addr) {
    asm volatile("ldmatrix.sync.aligned.m8n8.x4.shared.b16 {%0,%1,%2,%3}, [%4];"
                 : "=r"(r[0]), "=r"(r[1]), "=r"(r[2]), "=r"(r[3]) : "r"(addr));
}
__device__ __forceinline__ void ldsm4t(uint32_t (&r)[4], uint32_t addr) {
    asm volatile("ldmatrix.sync.aligned.m8n8.x4.trans.shared.b16 {%0,%1,%2,%3}, [%4];"
                 : "=r"(r[0]), "=r"(r[1]), "=r"(r[2]), "=r"(r[3]) : "r"(addr));
}
__device__ __forceinline__ void mma16816(float (&c)[4], const uint32_t (&a)[4],
                                         uint32_t b0, uint32_t b1) {
    asm volatile(
        "mma.sync.aligned.m16n8k16.row.col.f32.f16.f16.f32 "
        "{%0,%1,%2,%3}, {%4,%5,%6,%7}, {%8,%9}, {%0,%1,%2,%3};"
        : "+f"(c[0]), "+f"(c[1]), "+f"(c[2]), "+f"(c[3])
        : "r"(a[0]), "r"(a[1]), "r"(a[2]), "r"(a[3]), "r"(b0), "r"(b1));
}
__device__ __forceinline__ uint32_t pack_h2(float a, float b) {
    __half2 h = __floats2half2_rn(a, b);
    return *(uint32_t*)&h;
}

// ---------------- pre-pass: W fp32 -> fp16 (tiny) ----------------

__global__ void wconv_kernel(const float* __restrict__ W) {
    int i = blockIdx.x * 256 + threadIdx.x;
    g_wf16[i] = __float2half_rn(W[i]);
}

// ---------------- main GEMM ----------------

__global__ __launch_bounds__(NTHREADS, 2)
void conv1d_hmma_kernel(const float* __restrict__ x,
                        const float* __restrict__ bias,
                        float* __restrict__ out)
{
    extern __shared__ __align__(128) uint8_t smem[];
    const uint32_t sm = smem_u32(smem);

    const int tid  = threadIdx.x;
    const int wid  = tid >> 5;
    const int lane = tid & 31;

    const int f0  = blockIdx.x * 128;
    const int l0  = blockIdx.y * 128;
    const int img = blockIdx.z;

    const float* xb = x   + (size_t)img * (1024 * 256);
    float*       ob = out + (size_t)img * (LOUT * 256);

    // 4x2 warp grid, 32x64 warp tiles
    const int wm = (wid >> 1) * 32;
    const int wn = (wid & 1) * 64;

    const uint32_t a_lane = (uint32_t)(wm + (lane & 15)) * A_STRIDE + (lane >> 4) * 16;
    const uint32_t b_lane = (uint32_t)(lane & 15) * B_STRIDE
                          + (uint32_t)(wn + (lane >> 4) * 8) * 2;

    // ---- B staging: all 3 taps of chunk c into half (c&1) ----
    const int b_row = tid >> 3;
    const int b_cg  = tid & 7;
    const uint32_t b_dst = (uint32_t)b_row * B_STRIDE + b_cg * 32;

    auto stageB3 = [&](int c) {
        const uint32_t half_base = sm + OFF_B + (c & 1) * (3 * B_BYTES);
        #pragma unroll
        for (int tap = 0; tap < 3; ++tap) {
            const int kr = tap * 256 + c * 32 + b_row;
            const __half* src = g_wf16 + (size_t)kr * 256 + f0 + b_cg * 16;
            const uint32_t d = half_base + tap * B_BYTES + b_dst;
            cp16(d,      src);
            cp16(d + 16, src + 8);
        }
    };

    // ---- A fp32 staging (thread mapping SHARED with convA) ----
    auto stageAF32 = [&](int c) {
        const int buf = c & 1;
        #pragma unroll
        for (int rep = 0; rep < 2; ++rep) {
            const int item = tid + rep * 256;          // 260 half-rows
            if (rep == 0 || tid < 4) {
                const int row = item >> 1, seg = item & 1;
                int xr = l0 + row;
                if (xr > 1023) xr = 1023;              // feeds only guarded outputs
                const float* src = xb + (size_t)xr * 256 + c * 32 + seg * 16;
                const uint32_t d = sm + OFF_F + buf * F_BYTES
                                 + (uint32_t)row * F_STRIDE + seg * 64;
                cp16(d,      src);
                cp16(d + 16, src + 4);
                cp16(d + 32, src + 8);
                cp16(d + 48, src + 12);
            }
        }
    };

    // ---- convert own-thread staged f32 -> fp16 A tile (no barrier needed) ----
    auto convA = [&](int c) {
        const int buf = c & 1;
        const uint8_t* fb = smem + OFF_F + buf * F_BYTES;
        uint8_t*       ab = smem + OFF_A + buf * A_BYTES;
        #pragma unroll
        for (int rep = 0; rep < 2; ++rep) {
            const int item = tid + rep * 256;
            if (rep == 0 || tid < 4) {
                const int row = item >> 1, seg = item & 1;
                const float* s = (const float*)(fb + (uint32_t)row * F_STRIDE + seg * 64);
                float4 v0 = *(const float4*)(s);
                float4 v1 = *(const float4*)(s + 4);
                float4 v2 = *(const float4*)(s + 8);
                float4 v3 = *(const float4*)(s + 12);
                uint4 u0, u1;
                u0.x = pack_h2(v0.x, v0.y); u0.y = pack_h2(v0.z, v0.w);
                u0.z = pack_h2(v1.x, v1.y); u0.w = pack_h2(v1.z, v1.w);
                u1.x = pack_h2(v2.x, v2.y); u1.y = pack_h2(v2.z, v2.w);
                u1.z = pack_h2(v3.x, v3.y); u1.w = pack_h2(v3.z, v3.w);
                uint8_t* d = ab + (uint32_t)row * A_STRIDE + seg * 32;
                *(uint4*)(d)      = u0;
                *(uint4*)(d + 16) = u1;
            }
        }
    };

    float acc[2][8][4];
    #pragma unroll
    for (int mt = 0; mt < 2; ++mt)
        #pragma unroll
        for (int nt = 0; nt < 8; ++nt)
            #pragma unroll
            for (int q = 0; q < 4; ++q)
                acc[mt][nt][q] = 0.f;

    // ---- prologue: one group = {B chunk 0 (3 taps), Af32(0)} ----
    stageB3(0);
    stageAF32(0);
    cp_commit();
    cp_wait0();
    convA(0);          // own-thread data: no barrier needed between wait and conv
    __syncthreads();   // publish convA + B slots to all threads

    for (int c = 0; c < 8; ++c) {
        // stage next chunk (one async group; flies under this chunk's 96 MMAs)
        if (c < 7) {
            stageB3(c + 1);
            stageAF32(c + 1);
            cp_commit();
        }

        // ---- 3 tap MMA sub-blocks, no internal barriers ----
        const uint32_t sAc = sm + OFF_A + (c & 1) * A_BYTES;
        const uint32_t sBh = sm + OFF_B + (c & 1) * (3 * B_BYTES);
        #pragma unroll
        for (int tap = 0; tap < 3; ++tap) {
            const uint32_t sA = sAc + (uint32_t)tap * A_STRIDE;
            const uint32_t sB = sBh + tap * B_BYTES;
            #pragma unroll
            for (int ks = 0; ks < 2; ++ks) {
                uint32_t af[2][4];
                ldsm4(af[0], sA + a_lane + ks * 32);
                ldsm4(af[1], sA + a_lane + 16 * A_STRIDE + ks * 32);
                uint32_t bf[4][4];
                #pragma unroll
                for (int n2 = 0; n2 < 4; ++n2)
                    ldsm4t(bf[n2], sB + b_lane + ks * (16 * B_STRIDE) + n2 * 32);
                #pragma unroll
                for (int mt = 0; mt < 2; ++mt)
                    #pragma unroll
                    for (int n2 = 0; n2 < 4; ++n2) {
                        mma16816(acc[mt][2 * n2],     af[mt], bf[n2][0], bf[n2][1]);
                        mma16816(acc[mt][2 * n2 + 1], af[mt], bf[n2][2], bf[n2][3]);
                    }
            }
        }

        // ---- chunk end: wait next-chunk group, convert own A bytes, publish ----
        if (c < 7) {
            cp_wait0();        // group committed ~3 tap-blocks ago: latency covered
            convA(c + 1);      // own-thread staged bytes -> no pre-barrier needed
            __syncthreads();   // publish A fp16 + B half to all threads
        }
    }

    // ---- epilogue: bias + guarded store from registers ----
    const int g  = lane >> 2;
    const int tq = lane & 3;
    #pragma unroll
    for (int nt = 0; nt < 8; ++nt) {
        const int col = f0 + wn + nt * 8 + tq * 2;
        const float b0 = __ldg(bias + col);
        const float b1 = __ldg(bias + col + 1);
        #pragma unroll
        for (int mt = 0; mt < 2; ++mt) {
            const int r = l0 + wm + mt * 16 + g;
            if (r < LOUT) {
                float2 v = make_float2(acc[mt][nt][0] + b0, acc[mt][nt][1] + b1);
                *(float2*)(ob + (size_t)r * 256 + col) = v;
            }
            if (r + 8 < LOUT) {
                float2 v = make_float2(acc[mt][nt][2] + b0, acc[mt][nt][3] + b1);
                *(float2*)(ob + (size_t)(r + 8) * 256 + col) = v;
            }
        }
    }
}

}  // namespace

extern "C" void kernel_launch(void* const* d_in, const int* in_sizes, int n_in,
                              void* d_out, int out_size)
{
    const float* x  = (const float*)d_in[0];   // [8,32,1024,256]
    const float* w  = (const float*)d_in[1];   // [3,256,256]
    const float* b  = (const float*)d_in[2];   // [256]
    float* out      = (float*)d_out;           // [8,32,1022,256]

    wconv_kernel<<<768, 256>>>(w);             // tiny: W fp32 -> fp16

    cudaFuncSetAttribute(conv1d_hmma_kernel,
                         cudaFuncAttributeMaxDynamicSharedMemorySize, SMEM_TOTAL);

    dim3 grid(2, 8, 256);                      // f-tiles, m-tiles, images
    conv1d_hmma_kernel<<<grid, NTHREADS, SMEM_TOTAL>>>(x, b, out);
}